// round 10
// baseline (speedup 1.0000x reference)
#include <cuda_runtime.h>
#include <cuda_bf16.h>
#include <cstdint>

// Matvec: out[n] = sum_d fc[n][d] * input[d],  n = 50, d = 1048576.
//
// R8 conclusion: all LDG-based variants pin at ~5.8 TB/s because the same
// warps own fetch AND compute — reduction/barrier/tail time drains the HBM
// queues (duty cycle ~71%). Fix: producer/consumer decoupling via
// cp.async.bulk + mbarrier. Thread 0 of each CTA keeps NSTG stages of bulk
// copies in flight (5 rows x 2KB per stage); the copy engine feeds DRAM
// continuously while the other threads FMA out of smem. Static stage->CTA
// map keeps everything bit-deterministic.
// Grid: 296 CTAs (148 SMs x 2, one wave). group g = bid % 10 owns rows
// [5g,5g+5); pos p = bid/10 takes stages p, p+cpg, ... of that group.
// (R9 resubmit after infra flake; cp.async.bulk dst = shared::cta form.)

#define RPC   5
#define SF    512                  // floats per row per stage (2KB)
#define NSTG  4                    // pipeline depth (40KB smem)
#define NCTA  296

__device__ float g_partials[64 * 32];     // [row][pos]
__device__ int   g_arrive[16];            // zero-initialized

__device__ __forceinline__ uint32_t smem_u32(const void* p) {
    uint32_t a;
    asm("{ .reg .u64 t; cvta.to.shared.u64 t, %1; cvt.u32.u64 %0, t; }"
        : "=r"(a) : "l"(p));
    return a;
}
__device__ __forceinline__ void mbar_init(uint32_t m, uint32_t cnt) {
    asm volatile("mbarrier.init.shared.b64 [%0], %1;" :: "r"(m), "r"(cnt) : "memory");
}
__device__ __forceinline__ void mbar_expect_tx(uint32_t m, uint32_t bytes) {
    asm volatile("mbarrier.arrive.expect_tx.shared.b64 _, [%0], %1;"
                 :: "r"(m), "r"(bytes) : "memory");
}
__device__ __forceinline__ void mbar_arrive(uint32_t m) {
    asm volatile("mbarrier.arrive.shared.b64 _, [%0];" :: "r"(m) : "memory");
}
__device__ __forceinline__ void mbar_wait(uint32_t m, uint32_t ph) {
    asm volatile(
        "{\n\t.reg .pred P;\n\t"
        "L1_%=:\n\t"
        "mbarrier.try_wait.parity.acquire.cta.shared::cta.b64 P, [%0], %1, 0x989680;\n\t"
        "@P bra.uni L2_%=;\n\t"
        "bra.uni L1_%=;\n\t"
        "L2_%=:\n\t}"
        :: "r"(m), "r"(ph) : "memory");
}
// Relaxed wait: ONLY for the producer, whose post-wait smem writes go through
// the async proxy (cp.async.bulk), ordered by expect_tx/complete_tx.
__device__ __forceinline__ void mbar_wait_relaxed(uint32_t m, uint32_t ph) {
    asm volatile(
        "{\n\t.reg .pred P;\n\t"
        "L1_%=:\n\t"
        "mbarrier.try_wait.parity.relaxed.cta.shared::cta.b64 P, [%0], %1, 0x989680;\n\t"
        "@P bra.uni L2_%=;\n\t"
        "bra.uni L1_%=;\n\t"
        "L2_%=:\n\t}"
        :: "r"(m), "r"(ph) : "memory");
}
__device__ __forceinline__ void bulk_copy(uint32_t dst, const void* src,
                                          uint32_t bytes, uint32_t mbar) {
    asm volatile(
        "cp.async.bulk.shared::cta.global.mbarrier::complete_tx::bytes "
        "[%0], [%1], %2, [%3];"
        :: "r"(dst), "l"(src), "r"(bytes), "r"(mbar) : "memory");
}

__global__ void __launch_bounds__(256, 2) matvec_bulk_kernel(
    const float* __restrict__ inp,
    const float* __restrict__ fc,
    float* __restrict__ out,
    int D, int G)
{
    __shared__ float buf[NSTG][RPC][SF];          // 40KB
    __shared__ unsigned long long mbar_full[NSTG];
    __shared__ unsigned long long mbar_empty[NSTG];
    __shared__ float warp_sums[8][RPC];
    __shared__ bool is_last;

    const int tid  = threadIdx.x;
    const int b    = blockIdx.x;
    const int g    = b % G;                       // group: rows [5g, 5g+5)
    const int p    = b / G;                       // position within group
    const int cpg  = (gridDim.x - 1 - g) / G + 1; // CTAs in this group
    const int row0 = g * RPC;
    const int NST  = D / SF;                      // 2048 stages per group
    const int M    = (NST - p + cpg - 1) / cpg;   // my stage count

    const uint32_t full0  = smem_u32(&mbar_full[0]);
    const uint32_t empty0 = smem_u32(&mbar_empty[0]);
    const uint32_t bufb   = smem_u32(&buf[0][0][0]);

    if (tid == 0) {
        #pragma unroll
        for (int s = 0; s < NSTG; s++) {
            mbar_init(full0  + 8u * s, 1);
            mbar_init(empty0 + 8u * s, 256);
        }
    }
    __syncthreads();

    const float* fcg = fc + (size_t)row0 * D;

    // Prologue: fill up to NSTG stages.
    if (tid == 0) {
        for (int k = 0; k < NSTG && k < M; k++) {
            const int sg = p + k * cpg;           // global stage id
            const uint32_t fb = full0 + 8u * k;
            mbar_expect_tx(fb, RPC * SF * 4u);
            #pragma unroll
            for (int r = 0; r < RPC; r++)
                bulk_copy(bufb + ((k * RPC + r) * SF) * 4u,
                          fcg + (size_t)r * D + (size_t)sg * SF,
                          SF * 4u, fb);
        }
    }

    float a0 = 0.f, a1 = 0.f, a2 = 0.f, a3 = 0.f, a4 = 0.f;
    const int j = 2 * tid;                        // 2 d-positions per thread

    for (int it = 0; it < M; it++) {
        const int slot = it & (NSTG - 1);
        const uint32_t ph = (it / NSTG) & 1;
        const int sg = p + it * cpg;

        mbar_wait(full0 + 8u * slot, ph);         // acquire: smem data ready

        const float2 xin = *reinterpret_cast<const float2*>(inp + (size_t)sg * SF + j);
        const float* bs = &buf[slot][0][0];
        float2 f0 = *reinterpret_cast<const float2*>(bs + 0 * SF + j);
        float2 f1 = *reinterpret_cast<const float2*>(bs + 1 * SF + j);
        float2 f2 = *reinterpret_cast<const float2*>(bs + 2 * SF + j);
        float2 f3 = *reinterpret_cast<const float2*>(bs + 3 * SF + j);
        float2 f4 = *reinterpret_cast<const float2*>(bs + 4 * SF + j);
        a0 = fmaf(f0.x, xin.x, a0); a0 = fmaf(f0.y, xin.y, a0);
        a1 = fmaf(f1.x, xin.x, a1); a1 = fmaf(f1.y, xin.y, a1);
        a2 = fmaf(f2.x, xin.x, a2); a2 = fmaf(f2.y, xin.y, a2);
        a3 = fmaf(f3.x, xin.x, a3); a3 = fmaf(f3.y, xin.y, a3);
        a4 = fmaf(f4.x, xin.x, a4); a4 = fmaf(f4.y, xin.y, a4);

        mbar_arrive(empty0 + 8u * slot);          // done reading this slot

        // Producer: refill this slot for stage it+NSTG once all 256 readers
        // have arrived (includes our own arrival above).
        if (tid == 0 && it + NSTG < M) {
            mbar_wait_relaxed(empty0 + 8u * slot, ph);
            const int k   = it + NSTG;
            const int sg2 = p + k * cpg;
            const uint32_t fb = full0 + 8u * slot;
            mbar_expect_tx(fb, RPC * SF * 4u);
            #pragma unroll
            for (int r = 0; r < RPC; r++)
                bulk_copy(bufb + ((slot * RPC + r) * SF) * 4u,
                          fcg + (size_t)r * D + (size_t)sg2 * SF,
                          SF * 4u, fb);
        }
    }

    // Block reduction of the 5 accumulators.
    float s[RPC] = {a0, a1, a2, a3, a4};
    const int w = tid >> 5, lid = tid & 31;
    #pragma unroll
    for (int r = 0; r < RPC; r++) {
        float v = s[r];
        #pragma unroll
        for (int off = 16; off > 0; off >>= 1)
            v += __shfl_down_sync(0xFFFFFFFFu, v, off);
        if (lid == 0) warp_sums[w][r] = v;
    }
    __syncthreads();

    if (tid < RPC) {
        float v = 0.f;
        #pragma unroll
        for (int k = 0; k < 8; k++) v += warp_sums[k][tid];
        g_partials[(row0 + tid) * 32 + p] = v;
    }
    __syncthreads();
    if (tid == 0) {
        __threadfence();
        int old = atomicAdd(&g_arrive[g], 1);
        is_last = (old == cpg - 1);
    }
    __syncthreads();

    // Last CTA of group: deterministic fixed-order final sum (cpg <= 32).
    if (is_last) {
        __threadfence();                           // acquire partials
        if (w < RPC) {
            float v = (lid < cpg) ? g_partials[(row0 + w) * 32 + lid] : 0.f;
            #pragma unroll
            for (int off = 16; off > 0; off >>= 1)
                v += __shfl_down_sync(0xFFFFFFFFu, v, off);
            if (lid == 0) out[row0 + w] = v;
        }
        __syncthreads();
        if (tid == 0) g_arrive[g] = 0;             // reset for next replay
    }
}

extern "C" void kernel_launch(void* const* d_in, const int* in_sizes, int n_in,
                              void* d_out, int out_size)
{
    const float* inp = (const float*)d_in[0];   // [D]
    const float* fc  = (const float*)d_in[1];   // [N_ROWS, D]
    float* out       = (float*)d_out;           // [N_ROWS]

    const int D = in_sizes[0];
    const int G = out_size / RPC;               // 10 groups for 50 rows

    matvec_bulk_kernel<<<NCTA, 256>>>(inp, fc, out, D, G);
}

// round 13
// speedup vs baseline: 1.3684x; 1.3684x over previous
#include <cuda_runtime.h>
#include <cuda_bf16.h>

// Matvec: out[n] = sum_d fc[n][d] * input[d],  n = 50, d = 1048576.
//
// Experiment (unchanged from R11): CONTIGUOUS SLAB assignment — each CTA
// reads 5 strictly sequential ~57KB fc streams instead of 4KB jumps at
// 352KB stride, to maximize DRAM open-row hits. One wave: 740 CTAs = 148x5.
// R12 repackaging after two consecutive container failures on the previous
// build: 1D grid (740), no minBlocks launch-bounds hint, default unrolling.
// Kernel semantics identical.

#define RPC 5                      // rows per CTA group
#define CPG 74                     // CTAs per row-group (10*74=740 = 148*5)

__device__ float g_partials[64 * 80];
__device__ int   g_arrive[16];             // zero-initialized

__global__ void __launch_bounds__(256) matvec_slab_kernel(
    const float* __restrict__ inp,
    const float* __restrict__ fc,
    float* __restrict__ out,
    int D, int G)
{
    const int bid   = blockIdx.x;
    const int group = bid / CPG;             // rows [5g, 5g+5)
    const int cta   = bid - group * CPG;     // 0..CPG-1 within group
    const int row0  = group * RPC;
    const int vec_total = D / 4;             // 262144 float4 per row
    const int vpc   = (vec_total + CPG - 1) / CPG;   // 3543
    const int i_beg = cta * vpc;
    const int i_end = (i_beg + vpc < vec_total) ? (i_beg + vpc) : vec_total;

    const float4* __restrict__ a  = reinterpret_cast<const float4*>(inp);
    const float4* __restrict__ b0 = reinterpret_cast<const float4*>(fc + (size_t)(row0 + 0) * D);
    const float4* __restrict__ b1 = reinterpret_cast<const float4*>(fc + (size_t)(row0 + 1) * D);
    const float4* __restrict__ b2 = reinterpret_cast<const float4*>(fc + (size_t)(row0 + 2) * D);
    const float4* __restrict__ b3 = reinterpret_cast<const float4*>(fc + (size_t)(row0 + 3) * D);
    const float4* __restrict__ b4 = reinterpret_cast<const float4*>(fc + (size_t)(row0 + 4) * D);

    float s0 = 0.f, s1 = 0.f, s2 = 0.f, s3 = 0.f, s4 = 0.f;

    // Contiguous slab: 256-wide thread fronts sweep [i_beg, i_end), so each
    // of the 5 fc streams advances strictly sequentially (4KB per front).
    for (int i = i_beg + threadIdx.x; i < i_end; i += 256) {
        float4 av = __ldg(a + i);            // input: L2-resident
        float4 v0 = __ldcs(b0 + i);          // fc: streamed, evict-first
        float4 v1 = __ldcs(b1 + i);
        float4 v2 = __ldcs(b2 + i);
        float4 v3 = __ldcs(b3 + i);
        float4 v4 = __ldcs(b4 + i);

        s0 = fmaf(av.x, v0.x, s0); s0 = fmaf(av.y, v0.y, s0);
        s0 = fmaf(av.z, v0.z, s0); s0 = fmaf(av.w, v0.w, s0);
        s1 = fmaf(av.x, v1.x, s1); s1 = fmaf(av.y, v1.y, s1);
        s1 = fmaf(av.z, v1.z, s1); s1 = fmaf(av.w, v1.w, s1);
        s2 = fmaf(av.x, v2.x, s2); s2 = fmaf(av.y, v2.y, s2);
        s2 = fmaf(av.z, v2.z, s2); s2 = fmaf(av.w, v2.w, s2);
        s3 = fmaf(av.x, v3.x, s3); s3 = fmaf(av.y, v3.y, s3);
        s3 = fmaf(av.z, v3.z, s3); s3 = fmaf(av.w, v3.w, s3);
        s4 = fmaf(av.x, v4.x, s4); s4 = fmaf(av.y, v4.y, s4);
        s4 = fmaf(av.z, v4.z, s4); s4 = fmaf(av.w, v4.w, s4);
    }

    // Block reduction for the 5 row-sums.
    float s[RPC] = {s0, s1, s2, s3, s4};
    __shared__ float warp_sums[8][RPC];
    #pragma unroll
    for (int r = 0; r < RPC; r++) {
        float v = s[r];
        #pragma unroll
        for (int off = 16; off > 0; off >>= 1)
            v += __shfl_down_sync(0xFFFFFFFFu, v, off);
        if ((threadIdx.x & 31) == 0)
            warp_sums[threadIdx.x >> 5][r] = v;
    }
    __syncthreads();

    __shared__ bool is_last;
    if (threadIdx.x < RPC) {
        float v = 0.f;
        #pragma unroll
        for (int w = 0; w < 8; w++) v += warp_sums[w][threadIdx.x];
        g_partials[(row0 + threadIdx.x) * 80 + cta] = v;
    }
    __syncthreads();                 // partials visible before fence+count
    if (threadIdx.x == 0) {
        __threadfence();
        int old = atomicAdd(&g_arrive[group], 1);
        is_last = (old == CPG - 1);
    }
    __syncthreads();

    // Last CTA of the group: deterministic final sum of CPG partials per row.
    // Warp r handles row r; lanes cover partials lid, lid+32, lid+64(<74).
    if (is_last) {
        __threadfence();             // acquire
        const int w   = threadIdx.x >> 5;
        const int lid = threadIdx.x & 31;
        if (w < RPC) {
            const float* p = &g_partials[(row0 + w) * 80];
            float v = p[lid] + p[lid + 32];
            if (lid + 64 < CPG) v += p[lid + 64];
            #pragma unroll
            for (int off = 16; off > 0; off >>= 1)
                v += __shfl_down_sync(0xFFFFFFFFu, v, off);
            if (lid == 0)
                out[row0 + w] = v;
        }
        __syncthreads();
        if (threadIdx.x == 0)
            g_arrive[group] = 0;     // reset for next graph replay
    }
}

extern "C" void kernel_launch(void* const* d_in, const int* in_sizes, int n_in,
                              void* d_out, int out_size)
{
    const float* inp = (const float*)d_in[0];   // [D]
    const float* fc  = (const float*)d_in[1];   // [N_ROWS, D]
    float* out       = (float*)d_out;           // [N_ROWS]

    const int D = in_sizes[0];
    const int G = out_size / RPC;               // 10 groups for 50 rows

    matvec_slab_kernel<<<CPG * G, 256>>>(inp, fc, out, D, G);
}